// round 12
// baseline (speedup 1.0000x reference)
#include <cuda_runtime.h>
#include <cuda_fp16.h>
#include <cstdint>
#include <cstddef>

// ---------------------------------------------------------------------------
// data [S=1024, B=256, I=2], W_ih [256,2], b_ih[256], W_hh [256,256],
// b_hh[256], lin_W [2,256], lin_b[2]; out = softmax(h @ lin_W^T + lin_b).
//
// R12: OCCUPANCY-2 redesign. 64 clusters x 4 CTAs x 256 thr, 2 CTAs/SM.
// CTA rank r owns h cols [r*64, +64). Thread (hh = tid>>2, kc = tid&3):
// W_hh[col][kc*64..+64) in 32 u64 regs (64 fp32 regs -> fits 128-reg budget).
// Per step (ONE phase): 4 rows x 64 k fma.f32x2, 2-round shfl butterfly
// (lane kc ends with row kc's full sum), tanh, publish via 4x st.async
// (self + 3 peers) with complete_tx; one mbarrier per h buffer,
// expect_tx = 4096B (4 source CTAs x 1024B). R7's proven tx protocol.
// Co-resident CTAs are independent -> HW scheduler hides waits/tails.
// ---------------------------------------------------------------------------

#define S_LEN    1024
#define BATCH    256
#define HID      256
#define NTHREADS 256

#define QPAD   68                   // 64 floats + 4 pad per k-quarter
#define HROW   (4*QPAD)             // 272 floats per batch row
#define HPBUF  (4*HROW)             // 1088 floats (4 batch rows)
#define SMEM_FLOATS (2*HPBUF)       // 2176 floats = 8704 B

__device__ __half g_h[(size_t)S_LEN * BATCH * HID];   // 134 MB fp16 scratch

typedef unsigned long long u64;

__device__ __forceinline__ void fma2(u64& acc, u64 a, u64 b) {
    asm("fma.rn.f32x2 %0, %1, %2, %0;" : "+l"(acc) : "l"(a), "l"(b));
}
__device__ __forceinline__ float pairsum(u64 v) {
    return __uint_as_float((unsigned)(v & 0xffffffffull)) +
           __uint_as_float((unsigned)(v >> 32));
}
__device__ __forceinline__ float fast_tanh(float x) {
    float e = __expf(-2.0f * x);
    return __fdividef(1.0f - e, 1.0f + e);
}
__device__ __forceinline__ void mbar_wait(uint32_t mba, uint32_t par) {
    asm volatile(
        "{\n\t.reg .pred P;\n"
        "WL_%=:\n\t"
        "mbarrier.try_wait.parity.acquire.cluster.shared::cta.b64 P, [%0], %1, 0x989680;\n\t"
        "@P bra.uni WD_%=;\n\t"
        "bra.uni WL_%=;\n"
        "WD_%=:\n\t}"
        :: "r"(mba), "r"(par) : "memory");
}
__device__ __forceinline__ void st_async(uint32_t addr, uint32_t val, uint32_t mbar) {
    asm volatile("st.async.shared::cluster.mbarrier::complete_tx::bytes.u32 [%0], %1, [%2];"
                 :: "r"(addr), "r"(val), "r"(mbar) : "memory");
}

__global__ void __launch_bounds__(NTHREADS, 2) __cluster_dims__(4, 1, 1)
rnn_scan_kernel(const float* __restrict__ data,
                const float* __restrict__ W_ih,
                const float* __restrict__ b_ih,
                const float* __restrict__ W_hh,
                const float* __restrict__ b_hh)
{
    __shared__ __align__(16) float sm[SMEM_FLOATS];
    __shared__ __align__(8)  unsigned long long mb[2];   // [buf]

    const int tid = threadIdx.x;
    uint32_t rank;
    asm("mov.u32 %0, %%cluster_ctarank;" : "=r"(rank));
    const int g   = blockIdx.x >> 2;          // batch group of 4 rows
    const int hh  = tid >> 2;                 // column within CTA's 64-col slice
    const int kc  = tid & 3;                  // k-quarter this thread reduces
    const int col = (int)rank * 64 + hh;      // global output column
    const int myrow = kc;                     // batch row this lane finalizes

    // ---- init: zero h buf0 ----
    for (int i = tid; i < HPBUF; i += NTHREADS) sm[i] = 0.0f;

    // ---- W_hh quarter-row -> 32 u64 registers ----
    u64 W[32];
    {
        const float* wp = W_hh + (size_t)col * HID + kc * 64;
        #pragma unroll
        for (int j = 0; j < 16; ++j) {
            ulonglong2 t = *(const ulonglong2*)(wp + 4 * j);
            W[2 * j] = t.x; W[2 * j + 1] = t.y;
        }
    }
    const float biasv = b_ih[col] + b_hh[col];
    const float wih0  = W_ih[col * 2 + 0];
    const float wih1  = W_ih[col * 2 + 1];

    uint32_t sm_u32, mb_u32;
    asm("{ .reg .u64 t; cvta.to.shared.u64 t, %1; cvt.u32.u64 %0, t; }"
        : "=r"(sm_u32) : "l"(sm));
    asm("{ .reg .u64 t; cvta.to.shared.u64 t, %1; cvt.u32.u64 %0, t; }"
        : "=r"(mb_u32) : "l"(mb));
    uint32_t dst_sm[4], dst_mb[4];
    #pragma unroll
    for (int r = 0; r < 4; ++r) {
        asm("mapa.shared::cluster.u32 %0, %1, %2;"
            : "=r"(dst_sm[r]) : "r"(sm_u32), "r"((uint32_t)r));
        asm("mapa.shared::cluster.u32 %0, %1, %2;"
            : "=r"(dst_mb[r]) : "r"(mb_u32), "r"((uint32_t)r));
    }

    // count = 1: only tid0's expect_tx arrive; everything else is tx bytes
    if (tid < 2)
        asm volatile("mbarrier.init.shared.b64 [%0], %1;"
                     :: "r"(mb_u32 + (uint32_t)tid * 8u), "r"(1u) : "memory");
    __syncthreads();
    // all 4 CTAs' mbars + zeroed h must be live before any st.async traffic
    asm volatile("barrier.cluster.arrive.aligned;" ::: "memory");
    asm volatile("barrier.cluster.wait.aligned;"   ::: "memory");

    // x-term for step 0: x0 = [1, 0]
    float c = wih0 + biasv;

    for (int s = 0; s < S_LEN; ++s) {
        const int cur = s & 1, nxt = cur ^ 1;
        const uint32_t par = (uint32_t)(((s - 1) >> 1) & 1);

        // arm mb[nxt]: 4 CTAs x 256 threads x 4B = 4096B of st.async
        if (tid == 0)
            asm volatile("mbarrier.arrive.expect_tx.shared.b64 _, [%0], %1;"
                         :: "r"(mb_u32 + (uint32_t)nxt * 8u), "r"(4096u) : "memory");

        // prefetch x for step s+1 (x[s+1] = data[s]) into registers
        float2 xn;
        const bool havex = (s < S_LEN - 1);
        if (havex)
            xn = *(const float2*)(data + ((size_t)s * BATCH + g * 4 + myrow) * 2);

        // gate: all 4 rows of h_s fully present (self + 3 peers st.async)
        if (s > 0) mbar_wait(mb_u32 + (uint32_t)cur * 8u, par);

        // ---- FMA: 4 rows x 64 k (own k-quarter), W in regs ----
        const float* hb = sm + cur * HPBUF + kc * QPAD;
        u64 a0 = 0, a1 = 0, a2 = 0, a3 = 0;
        #pragma unroll
        for (int j = 0; j < 16; ++j) {
            const int k = 4 * j;
            ulonglong2 h0 = *(const ulonglong2*)(hb + 0 * HROW + k);
            ulonglong2 h1 = *(const ulonglong2*)(hb + 1 * HROW + k);
            ulonglong2 h2 = *(const ulonglong2*)(hb + 2 * HROW + k);
            ulonglong2 h3 = *(const ulonglong2*)(hb + 3 * HROW + k);
            fma2(a0, W[2*j], h0.x); fma2(a0, W[2*j+1], h0.y);
            fma2(a1, W[2*j], h1.x); fma2(a1, W[2*j+1], h1.y);
            fma2(a2, W[2*j], h2.x); fma2(a2, W[2*j+1], h2.y);
            fma2(a3, W[2*j], h3.x); fma2(a3, W[2*j+1], h3.y);
        }
        float p0 = pairsum(a0);
        float p1 = pairsum(a1);
        float p2 = pairsum(a2);
        float p3 = pairsum(a3);

        // ---- butterfly: lane kc ends with row kc's full 256-k sum ----
        // round 1 (xor 1): send the rows the partner keeps
        const int kb = kc & 1;
        float s1 = kb ? p0 : p1;          // partner keeps row (kb^1)
        float s2 = kb ? p2 : p3;          // and row 2+(kb^1)
        float r1 = __shfl_xor_sync(0xffffffffu, s1, 1);
        float r2 = __shfl_xor_sync(0xffffffffu, s2, 1);
        float m1 = (kb ? p1 : p0) + r1;   // row kb over merged k-half
        float m2 = (kb ? p3 : p2) + r2;   // row 2+kb over merged k-half
        // round 2 (xor 2): partner keeps the other row slot
        float snd = (kc < 2) ? m2 : m1;
        float rcv = __shfl_xor_sync(0xffffffffu, snd, 2);
        float tot = ((kc < 2) ? m1 : m2) + rcv;   // row kc, full k

        float v = fast_tanh(c + tot);

        // ---- publish h_{s+1}[row kc][col] to all 4 CTAs ----
        const uint32_t slot =
            (uint32_t)(nxt * HPBUF + myrow * HROW + (int)rank * QPAD + hh) * 4u;
        const uint32_t mbo = (uint32_t)nxt * 8u;
        const uint32_t vv  = __float_as_uint(v);
        st_async(dst_sm[0] + slot, vv, dst_mb[0] + mbo);
        st_async(dst_sm[1] + slot, vv, dst_mb[1] + mbo);
        st_async(dst_sm[2] + slot, vv, dst_mb[2] + mbo);
        st_async(dst_sm[3] + slot, vv, dst_mb[3] + mbo);

        // off the critical path: persist for the head kernel, next x-term
        g_h[((size_t)s * BATCH + g * 4 + myrow) * HID + col] = __float2half(v);
        if (havex) c = fmaf(xn.x, wih0, fmaf(xn.y, wih1, biasv));
    }

    // keep smem/mbars alive until peers' trailing async traffic drains
    asm volatile("barrier.cluster.arrive.aligned;" ::: "memory");
    asm volatile("barrier.cluster.wait.aligned;"   ::: "memory");
}

// ---------------------------------------------------------------------------
// Head: logits = h @ lin_W^T + lin_b, softmax over I=2.
// One warp per TWO (s,b) rows; uint4 (8-half) loads, both issued up front.
// ---------------------------------------------------------------------------
__global__ void __launch_bounds__(256)
rnn_head_kernel(const float* __restrict__ lin_W,
                const float* __restrict__ lin_b,
                float* __restrict__ out)
{
    __shared__ float w0s[HID], w1s[HID], lbs[2];
    const int tid = threadIdx.x;
    if (tid < HID) { w0s[tid] = lin_W[tid]; w1s[tid] = lin_W[HID + tid]; }
    if (tid < 2)   lbs[tid] = lin_b[tid];
    __syncthreads();

    const int lane = tid & 31;
    const size_t sb0 = (size_t)blockIdx.x * 16 + (tid >> 5) * 2;

    // both rows' loads issued back-to-back (2x MLP)
    uint4 v0 = *(const uint4*)(g_h + sb0 * HID + lane * 8);
    uint4 v1 = *(const uint4*)(g_h + (sb0 + 1) * HID + lane * 8);

    float4 wa0 = *(const float4*)(w0s + lane * 8);
    float4 wa1 = *(const float4*)(w0s + lane * 8 + 4);
    float4 wb0 = *(const float4*)(w1s + lane * 8);
    float4 wb1 = *(const float4*)(w1s + lane * 8 + 4);

    #pragma unroll
    for (int r = 0; r < 2; ++r) {
        uint4 v = r ? v1 : v0;
        float2 h0 = __half22float2(*(const __half2*)&v.x);
        float2 h1 = __half22float2(*(const __half2*)&v.y);
        float2 h2 = __half22float2(*(const __half2*)&v.z);
        float2 h3 = __half22float2(*(const __half2*)&v.w);

        float acc0 = h0.x*wa0.x + h0.y*wa0.y + h1.x*wa0.z + h1.y*wa0.w
                   + h2.x*wa1.x + h2.y*wa1.y + h3.x*wa1.z + h3.y*wa1.w;
        float acc1 = h0.x*wb0.x + h0.y*wb0.y + h1.x*wb0.z + h1.y*wb0.w
                   + h2.x*wb1.x + h2.y*wb1.y + h3.x*wb1.z + h3.y*wb1.w;

        #pragma unroll
        for (int m = 16; m; m >>= 1) {
            acc0 += __shfl_xor_sync(0xffffffffu, acc0, m);
            acc1 += __shfl_xor_sync(0xffffffffu, acc1, m);
        }
        if (lane == 0) {
            float l0 = acc0 + lbs[0], l1 = acc1 + lbs[1];
            float mx = fmaxf(l0, l1);
            float e0 = expf(l0 - mx), e1 = expf(l1 - mx);
            float inv = 1.0f / (e0 + e1);
            float2 o; o.x = e0 * inv; o.y = e1 * inv;
            *(float2*)(out + (sb0 + r) * 2) = o;
        }
    }
}

// ---------------------------------------------------------------------------
extern "C" void kernel_launch(void* const* d_in, const int* in_sizes, int n_in,
                              void* d_out, int out_size)
{
    (void)in_sizes; (void)n_in; (void)out_size;
    const float* data  = (const float*)d_in[0];
    const float* W_ih  = (const float*)d_in[1];
    const float* b_ih  = (const float*)d_in[2];
    const float* W_hh  = (const float*)d_in[3];
    const float* b_hh  = (const float*)d_in[4];
    const float* lin_W = (const float*)d_in[5];
    const float* lin_b = (const float*)d_in[6];
    float* out = (float*)d_out;

    // 64 clusters x 4 CTAs, 2 CTAs/SM (128 regs) -> 128 SMs, 16 warps/SM
    rnn_scan_kernel<<<256, NTHREADS>>>(data, W_ih, b_ih, W_hh, b_hh);
    // 262144 (s,b) rows, 2 per warp, 8 warps per block -> 16384 blocks
    rnn_head_kernel<<<(S_LEN * BATCH) / 16, 256>>>(lin_W, lin_b, out);
}

// round 13
// speedup vs baseline: 1.1905x; 1.1905x over previous
#include <cuda_runtime.h>
#include <cuda_fp16.h>
#include <cstdint>
#include <cstddef>

// ---------------------------------------------------------------------------
// data [S=1024, B=256, I=2], W_ih [256,2], b_ih[256], W_hh [256,256],
// b_hh[256], lin_W [2,256], lin_b[2]; out = softmax(h @ lin_W^T + lin_b).
//
// R13 = R7's two-phase tx-pipeline, 512 threads/CTA, k-QUARTER split.
// 64 clusters x 2 CTAs (proven placement). CTA rank r owns cols [r*128,+128).
// Thread (hh = tid>>2, kc = tid&3): W_hh[col][kc*64..+64) in 32 u64 regs
// -> ~105 regs/thread, 512 thr/CTA => 16 warps/SM (2x R7) for HW latency
// hiding of the tail/wait residual. Exchange protocol (st.async complete_tx,
// pair barriers, expect_tx 2048B) is R7 byte-for-byte.
// Reduction: xor1 merges quarter pairs, xor2 completes; lanes kc<2 publish.
// ---------------------------------------------------------------------------

#define S_LEN    1024
#define BATCH    256
#define HID      256
#define NTHREADS 512

#define QPAD   68                   // 64 floats + 4 pad per k-quarter
#define HROW   (4*QPAD)             // 272 floats per batch row
#define HPBUF  (4*HROW)             // 1088 floats (4 batch rows)
#define SMEM_FLOATS (2*HPBUF)       // 2176 floats = 8704 B

__device__ __half g_h[(size_t)S_LEN * BATCH * HID];   // 134 MB fp16 scratch

typedef unsigned long long u64;

__device__ __forceinline__ void fma2(u64& acc, u64 a, u64 b) {
    asm("fma.rn.f32x2 %0, %1, %2, %0;" : "+l"(acc) : "l"(a), "l"(b));
}
__device__ __forceinline__ u64 add2(u64 a, u64 b) {
    u64 r; asm("add.rn.f32x2 %0, %1, %2;" : "=l"(r) : "l"(a), "l"(b)); return r;
}
__device__ __forceinline__ float pairsum(u64 v) {
    return __uint_as_float((unsigned)(v & 0xffffffffull)) +
           __uint_as_float((unsigned)(v >> 32));
}
__device__ __forceinline__ float fast_tanh(float x) {
    float e = __expf(-2.0f * x);
    return __fdividef(1.0f - e, 1.0f + e);
}
__device__ __forceinline__ void mbar_wait(uint32_t mba, uint32_t par) {
    asm volatile(
        "{\n\t.reg .pred P;\n"
        "WL_%=:\n\t"
        "mbarrier.try_wait.parity.acquire.cluster.shared::cta.b64 P, [%0], %1, 0x989680;\n\t"
        "@P bra.uni WD_%=;\n\t"
        "bra.uni WL_%=;\n"
        "WD_%=:\n\t}"
        :: "r"(mba), "r"(par) : "memory");
}
__device__ __forceinline__ void st_async(uint32_t addr, uint32_t val, uint32_t mbar) {
    asm volatile("st.async.shared::cluster.mbarrier::complete_tx::bytes.u32 [%0], %1, [%2];"
                 :: "r"(addr), "r"(val), "r"(mbar) : "memory");
}

__global__ void __launch_bounds__(NTHREADS, 1) __cluster_dims__(2, 1, 1)
rnn_scan_kernel(const float* __restrict__ data,
                const float* __restrict__ W_ih,
                const float* __restrict__ b_ih,
                const float* __restrict__ W_hh,
                const float* __restrict__ b_hh)
{
    __shared__ __align__(16) float sm[SMEM_FLOATS];
    __shared__ __align__(8)  unsigned long long mb[4];   // [pair*2 + buf]

    const int tid = threadIdx.x;
    uint32_t rank;
    asm("mov.u32 %0, %%cluster_ctarank;" : "=r"(rank));
    const int g   = blockIdx.x >> 1;          // batch group of 4 rows
    const int hh  = tid >> 2;                 // column within half (0..127)
    const int kc  = tid & 3;                  // k-quarter this thread reduces
    const int col = (int)rank * 128 + hh;     // global output column
    const int rsel = kc & 1;                  // row-within-pair this lane owns
    const int rowA = rsel;                    // row finalized in phase A
    const int rowB = 2 + rsel;                // row finalized in phase B
    const bool pub = (kc < 2);                // lanes 0,1 of each group publish

    // ---- init: zero h buf0 ----
    for (int i = tid; i < HPBUF; i += NTHREADS) sm[i] = 0.0f;

    // ---- W_hh quarter-row -> 32 u64 registers ----
    u64 W[32];
    {
        const float* wp = W_hh + (size_t)col * HID + kc * 64;
        #pragma unroll
        for (int j = 0; j < 16; ++j) {
            ulonglong2 t = *(const ulonglong2*)(wp + 4 * j);
            W[2 * j] = t.x; W[2 * j + 1] = t.y;
        }
    }
    const float biasv = b_ih[col] + b_hh[col];
    const float wih0  = W_ih[col * 2 + 0];
    const float wih1  = W_ih[col * 2 + 1];

    uint32_t sm_u32, mb_u32;
    asm("{ .reg .u64 t; cvta.to.shared.u64 t, %1; cvt.u32.u64 %0, t; }"
        : "=r"(sm_u32) : "l"(sm));
    asm("{ .reg .u64 t; cvta.to.shared.u64 t, %1; cvt.u32.u64 %0, t; }"
        : "=r"(mb_u32) : "l"(mb));
    uint32_t self_sm, self_mb, peer_sm, peer_mb;
    asm("mapa.shared::cluster.u32 %0, %1, %2;" : "=r"(self_sm) : "r"(sm_u32), "r"(rank));
    asm("mapa.shared::cluster.u32 %0, %1, %2;" : "=r"(self_mb) : "r"(mb_u32), "r"(rank));
    asm("mapa.shared::cluster.u32 %0, %1, %2;" : "=r"(peer_sm) : "r"(sm_u32), "r"(rank ^ 1u));
    asm("mapa.shared::cluster.u32 %0, %1, %2;" : "=r"(peer_mb) : "r"(mb_u32), "r"(rank ^ 1u));

    // count = 1: only tid0's expect_tx arrive; everything else is tx bytes
    if (tid < 4)
        asm volatile("mbarrier.init.shared.b64 [%0], %1;"
                     :: "r"(mb_u32 + (uint32_t)tid * 8u), "r"(1u) : "memory");
    __syncthreads();
    // peer mbars + zeroed h must be live before any st.async traffic
    asm volatile("barrier.cluster.arrive.aligned;" ::: "memory");
    asm volatile("barrier.cluster.wait.aligned;"   ::: "memory");

    // x-term constants for step 0: x0 = [1, 0]
    float cA = wih0 + biasv;
    float cB = wih0 + biasv;

    // hoisted: padded column offset within a row (quarter layout)
    const int colq = (col >> 6) * QPAD + (col & 63);

    for (int s = 0; s < S_LEN; ++s) {
        const int cur = s & 1, nxt = cur ^ 1;
        const uint32_t par = (uint32_t)(((s - 1) >> 1) & 1);

        // arm both pair-barriers for buf[nxt] (2048B of st.async each)
        if (tid == 0) {
            asm volatile("mbarrier.arrive.expect_tx.shared.b64 _, [%0], %1;"
                         :: "r"(mb_u32 + (uint32_t)(0 + nxt) * 8u), "r"(2048u) : "memory");
            asm volatile("mbarrier.arrive.expect_tx.shared.b64 _, [%0], %1;"
                         :: "r"(mb_u32 + (uint32_t)(2 + nxt) * 8u), "r"(2048u) : "memory");
        }

        // prefetch x for step s+1 (x[s+1] = data[s]) into registers
        float2 xnA, xnB;
        const bool havex = (s < S_LEN - 1);
        if (havex) {
            const float* xb = data + (size_t)s * BATCH * 2;
            xnA = *(const float2*)(xb + (g * 4 + rowA) * 2);
            xnB = *(const float2*)(xb + (g * 4 + rowB) * 2);
        }

        #pragma unroll
        for (int p = 0; p < 2; ++p) {
            // gate: rows 2p,2p+1 of h_s fully present (self + peer st.async)
            if (s > 0) mbar_wait(mb_u32 + (uint32_t)(p * 2 + cur) * 8u, par);

            // ---- FMA rows 2p, 2p+1 over own k-quarter (64 k) ----
            const float* hb = sm + cur * HPBUF + p * 2 * HROW + kc * QPAD;
            u64 a0 = 0, a1 = 0, b0 = 0, b1 = 0;
            #pragma unroll
            for (int j = 0; j < 16; ++j) {
                const int k = 4 * j;
                ulonglong2 h0 = *(const ulonglong2*)(hb + k);
                ulonglong2 h1 = *(const ulonglong2*)(hb + HROW + k);
                fma2(a0, W[2*j], h0.x); fma2(a1, W[2*j+1], h0.y);
                fma2(b0, W[2*j], h1.x); fma2(b1, W[2*j+1], h1.y);
            }
            float p0 = pairsum(add2(a0, a1));   // partial, row 2p (my quarter)
            float p1 = pairsum(add2(b0, b1));   // partial, row 2p+1

            // butterfly over the 4 k-quarter lanes of this column
            float q0 = __shfl_xor_sync(0xffffffffu, p0, 1);
            float q1 = __shfl_xor_sync(0xffffffffu, p1, 1);
            float r0m = p0 + q0;                // row 2p   over quarter-pair
            float r1m = p1 + q1;                // row 2p+1 over quarter-pair
            float keep = (rsel == 0) ? r0m : r1m;
            float tot  = keep + __shfl_xor_sync(0xffffffffu, keep, 2);

            float v = fast_tanh(((p == 0) ? cA : cB) + tot);

            // ---- publish row (2p + rsel): lanes kc<2 only (one per value) ----
            if (pub) {
                const int row = 2 * p + rsel;
                const uint32_t slot =
                    (uint32_t)(nxt * HPBUF + row * HROW + colq) * 4u;
                const uint32_t mbo = (uint32_t)(p * 2 + nxt) * 8u;
                const uint32_t vv  = __float_as_uint(v);
                st_async(self_sm + slot, vv, self_mb + mbo);
                st_async(peer_sm + slot, vv, peer_mb + mbo);
                // off the critical path: persist for the head kernel
                g_h[((size_t)s * BATCH + g * 4 + row) * HID + col] = __float2half(v);
            }
        }

        // x-terms for step s+1 (independent math; hidden under the loop)
        if (havex) {
            cA = fmaf(xnA.x, wih0, fmaf(xnA.y, wih1, biasv));
            cB = fmaf(xnB.x, wih0, fmaf(xnB.y, wih1, biasv));
        }
    }

    // keep smem/mbars alive until peer's trailing async traffic drains
    asm volatile("barrier.cluster.arrive.aligned;" ::: "memory");
    asm volatile("barrier.cluster.wait.aligned;"   ::: "memory");
}

// ---------------------------------------------------------------------------
// Head: logits = h @ lin_W^T + lin_b, softmax over I=2.
// One warp per TWO (s,b) rows; uint4 (8-half) loads, both issued up front.
// ---------------------------------------------------------------------------
__global__ void __launch_bounds__(256)
rnn_head_kernel(const float* __restrict__ lin_W,
                const float* __restrict__ lin_b,
                float* __restrict__ out)
{
    __shared__ float w0s[HID], w1s[HID], lbs[2];
    const int tid = threadIdx.x;
    if (tid < HID) { w0s[tid] = lin_W[tid]; w1s[tid] = lin_W[HID + tid]; }
    if (tid < 2)   lbs[tid] = lin_b[tid];
    __syncthreads();

    const int lane = tid & 31;
    const size_t sb0 = (size_t)blockIdx.x * 16 + (tid >> 5) * 2;

    // both rows' loads issued back-to-back (2x MLP)
    uint4 v0 = *(const uint4*)(g_h + sb0 * HID + lane * 8);
    uint4 v1 = *(const uint4*)(g_h + (sb0 + 1) * HID + lane * 8);

    float4 wa0 = *(const float4*)(w0s + lane * 8);
    float4 wa1 = *(const float4*)(w0s + lane * 8 + 4);
    float4 wb0 = *(const float4*)(w1s + lane * 8);
    float4 wb1 = *(const float4*)(w1s + lane * 8 + 4);

    #pragma unroll
    for (int r = 0; r < 2; ++r) {
        uint4 v = r ? v1 : v0;
        float2 h0 = __half22float2(*(const __half2*)&v.x);
        float2 h1 = __half22float2(*(const __half2*)&v.y);
        float2 h2 = __half22float2(*(const __half2*)&v.z);
        float2 h3 = __half22float2(*(const __half2*)&v.w);

        float acc0 = h0.x*wa0.x + h0.y*wa0.y + h1.x*wa0.z + h1.y*wa0.w
                   + h2.x*wa1.x + h2.y*wa1.y + h3.x*wa1.z + h3.y*wa1.w;
        float acc1 = h0.x*wb0.x + h0.y*wb0.y + h1.x*wb0.z + h1.y*wb0.w
                   + h2.x*wb1.x + h2.y*wb1.y + h3.x*wb1.z + h3.y*wb1.w;

        #pragma unroll
        for (int m = 16; m; m >>= 1) {
            acc0 += __shfl_xor_sync(0xffffffffu, acc0, m);
            acc1 += __shfl_xor_sync(0xffffffffu, acc1, m);
        }
        if (lane == 0) {
            float l0 = acc0 + lbs[0], l1 = acc1 + lbs[1];
            float mx = fmaxf(l0, l1);
            float e0 = expf(l0 - mx), e1 = expf(l1 - mx);
            float inv = 1.0f / (e0 + e1);
            float2 o; o.x = e0 * inv; o.y = e1 * inv;
            *(float2*)(out + (sb0 + r) * 2) = o;
        }
    }
}

// ---------------------------------------------------------------------------
extern "C" void kernel_launch(void* const* d_in, const int* in_sizes, int n_in,
                              void* d_out, int out_size)
{
    (void)in_sizes; (void)n_in; (void)out_size;
    const float* data  = (const float*)d_in[0];
    const float* W_ih  = (const float*)d_in[1];
    const float* b_ih  = (const float*)d_in[2];
    const float* W_hh  = (const float*)d_in[3];
    const float* b_hh  = (const float*)d_in[4];
    const float* lin_W = (const float*)d_in[5];
    const float* lin_b = (const float*)d_in[6];
    float* out = (float*)d_out;

    // 64 clusters x 2 CTAs (proven placement), 512 thr/CTA -> 16 warps/SM
    rnn_scan_kernel<<<128, NTHREADS>>>(data, W_ih, b_ih, W_hh, b_hh);
    // 262144 (s,b) rows, 2 per warp, 8 warps per block -> 16384 blocks
    rnn_head_kernel<<<(S_LEN * BATCH) / 16, 256>>>(lin_W, lin_b, out);
}

// round 14
// speedup vs baseline: 2.2334x; 1.8761x over previous
#include <cuda_runtime.h>
#include <cuda_fp16.h>
#include <cstdint>
#include <cstddef>

// ---------------------------------------------------------------------------
// data [S=1024, B=256, I=2], W_ih [256,2], b_ih[256], W_hh [256,256],
// b_hh[256], lin_W [2,256], lin_b[2]; out = softmax(h @ lin_W^T + lin_b).
//
// R14 = R11/R7 scan kernel BYTE-IDENTICAL (1286 us measured; every
// structural variant R8-R13 regressed 300-1600 us -> sharp local optimum,
// frozen) + head kernel with 4 rows/warp (4 independent uint4 loads,
// 2x MLP vs R11's head; isolated change, zero scan risk).
// ---------------------------------------------------------------------------

#define S_LEN    1024
#define BATCH    256
#define HID      256
#define NTHREADS 256

#define HROW   264                  // 128 | pad4 | 128 | pad4
#define HPBUF  (4*HROW)             // 4 batch rows
#define SMEM_FLOATS (2*HPBUF)       // 2112 floats = 8448 B

__device__ __half g_h[(size_t)S_LEN * BATCH * HID];   // 134 MB fp16 scratch

typedef unsigned long long u64;

__device__ __forceinline__ void fma2(u64& acc, u64 a, u64 b) {
    asm("fma.rn.f32x2 %0, %1, %2, %0;" : "+l"(acc) : "l"(a), "l"(b));
}
__device__ __forceinline__ u64 add2(u64 a, u64 b) {
    u64 r; asm("add.rn.f32x2 %0, %1, %2;" : "=l"(r) : "l"(a), "l"(b)); return r;
}
__device__ __forceinline__ float pairsum(u64 v) {
    return __uint_as_float((unsigned)(v & 0xffffffffull)) +
           __uint_as_float((unsigned)(v >> 32));
}
__device__ __forceinline__ float fast_tanh(float x) {
    float e = __expf(-2.0f * x);
    return __fdividef(1.0f - e, 1.0f + e);
}
__device__ __forceinline__ void mbar_wait(uint32_t mba, uint32_t par) {
    asm volatile(
        "{\n\t.reg .pred P;\n"
        "WL_%=:\n\t"
        "mbarrier.try_wait.parity.acquire.cluster.shared::cta.b64 P, [%0], %1, 0x989680;\n\t"
        "@P bra.uni WD_%=;\n\t"
        "bra.uni WL_%=;\n"
        "WD_%=:\n\t}"
        :: "r"(mba), "r"(par) : "memory");
}

__global__ void __launch_bounds__(NTHREADS, 1) __cluster_dims__(2, 1, 1)
rnn_scan_kernel(const float* __restrict__ data,
                const float* __restrict__ W_ih,
                const float* __restrict__ b_ih,
                const float* __restrict__ W_hh,
                const float* __restrict__ b_hh)
{
    __shared__ __align__(16) float sm[SMEM_FLOATS];
    __shared__ __align__(8)  unsigned long long mb[4];   // [pair*2 + buf]

    const int tid = threadIdx.x;
    uint32_t rank;
    asm("mov.u32 %0, %%cluster_ctarank;" : "=r"(rank));
    const int g   = blockIdx.x >> 1;          // batch group of 4 rows
    const int hh  = tid >> 1;                 // column within half
    const int kc  = tid & 1;                  // k-half this thread reduces
    const int col = (int)rank * 128 + hh;     // global output column
    const int rowA = kc;                      // row finalized in phase A
    const int rowB = 2 + kc;                  // row finalized in phase B

    // ---- init: zero h buf0 ----
    for (int i = tid; i < HPBUF; i += NTHREADS) sm[i] = 0.0f;

    // ---- W_hh half-row -> 64 u64 registers ----
    u64 W[64];
    {
        const float* wp = W_hh + (size_t)col * HID + kc * 128;
        #pragma unroll
        for (int j = 0; j < 32; ++j) {
            ulonglong2 t = *(const ulonglong2*)(wp + 4 * j);
            W[2 * j] = t.x; W[2 * j + 1] = t.y;
        }
    }
    const float biasv = b_ih[col] + b_hh[col];
    const float wih0  = W_ih[col * 2 + 0];
    const float wih1  = W_ih[col * 2 + 1];

    uint32_t sm_u32, mb_u32;
    asm("{ .reg .u64 t; cvta.to.shared.u64 t, %1; cvt.u32.u64 %0, t; }"
        : "=r"(sm_u32) : "l"(sm));
    asm("{ .reg .u64 t; cvta.to.shared.u64 t, %1; cvt.u32.u64 %0, t; }"
        : "=r"(mb_u32) : "l"(mb));
    uint32_t self_sm, self_mb, peer_sm, peer_mb;
    asm("mapa.shared::cluster.u32 %0, %1, %2;"
        : "=r"(self_sm) : "r"(sm_u32), "r"(rank));
    asm("mapa.shared::cluster.u32 %0, %1, %2;"
        : "=r"(self_mb) : "r"(mb_u32), "r"(rank));
    asm("mapa.shared::cluster.u32 %0, %1, %2;"
        : "=r"(peer_sm) : "r"(sm_u32), "r"(rank ^ 1u));
    asm("mapa.shared::cluster.u32 %0, %1, %2;"
        : "=r"(peer_mb) : "r"(mb_u32), "r"(rank ^ 1u));

    // count = 1: only tid0's expect_tx arrive; everything else is tx bytes
    if (tid < 4)
        asm volatile("mbarrier.init.shared.b64 [%0], %1;"
                     :: "r"(mb_u32 + (uint32_t)tid * 8u), "r"(1u) : "memory");
    __syncthreads();
    // peer mbars + zeroed h must be live before any st.async traffic
    asm volatile("barrier.cluster.arrive.aligned;" ::: "memory");
    asm volatile("barrier.cluster.wait.aligned;"   ::: "memory");

    // x-term constants for step 0: x0 = [1, 0]
    float cA = wih0 + biasv;
    float cB = wih0 + biasv;

    for (int s = 0; s < S_LEN; ++s) {
        const int cur = s & 1, nxt = cur ^ 1;
        const uint32_t par = (uint32_t)(((s - 1) >> 1) & 1);

        // arm both pair-barriers for buf[nxt] (2048B of st.async each)
        if (tid == 0) {
            asm volatile("mbarrier.arrive.expect_tx.shared.b64 _, [%0], %1;"
                         :: "r"(mb_u32 + (uint32_t)(0 + nxt) * 8u), "r"(2048u) : "memory");
            asm volatile("mbarrier.arrive.expect_tx.shared.b64 _, [%0], %1;"
                         :: "r"(mb_u32 + (uint32_t)(2 + nxt) * 8u), "r"(2048u) : "memory");
        }

        // prefetch x for step s+1 (x[s+1] = data[s]) into registers
        float2 xnA, xnB;
        const bool havex = (s < S_LEN - 1);
        if (havex) {
            const float* xb = data + (size_t)s * BATCH * 2;
            xnA = *(const float2*)(xb + (g * 4 + rowA) * 2);
            xnB = *(const float2*)(xb + (g * 4 + rowB) * 2);
        }

        #pragma unroll
        for (int p = 0; p < 2; ++p) {
            // gate: rows 2p,2p+1 of h_s fully present (self + peer st.async)
            if (s > 0) mbar_wait(mb_u32 + (uint32_t)(p * 2 + cur) * 8u, par);

            // ---- FMA rows 2p, 2p+1 over own k-half ----
            const float* hb = sm + cur * HPBUF + p * 2 * HROW + kc * 132;
            u64 a0 = 0, a1 = 0, b0 = 0, b1 = 0;
            #pragma unroll
            for (int j = 0; j < 32; ++j) {
                const int k = 4 * j;
                ulonglong2 h0 = *(const ulonglong2*)(hb + k);
                ulonglong2 h1 = *(const ulonglong2*)(hb + HROW + k);
                fma2(a0, W[2*j], h0.x); fma2(a1, W[2*j+1], h0.y);
                fma2(b0, W[2*j], h1.x); fma2(b1, W[2*j+1], h1.y);
            }
            float p0 = pairsum(add2(a0, a1));   // partial, row 2p
            float p1 = pairsum(add2(b0, b1));   // partial, row 2p+1

            // cross-k-half reduction with partner lane (lane^1, same column)
            float q0 = __shfl_xor_sync(0xffffffffu, p0, 1);
            float q1 = __shfl_xor_sync(0xffffffffu, p1, 1);
            float t  = (kc == 0) ? (p0 + q0) : (p1 + q1);
            float v  = fast_tanh(((p == 0) ? cA : cB) + t);

            // ---- publish row (2p + kc) of h_{s+1}: self + peer st.async ----
            const int row = 2 * p + kc;
            const uint32_t slot =
                (uint32_t)(nxt * HPBUF + row * HROW + (int)rank * 132 + hh) * 4u;
            const uint32_t mbo = (uint32_t)(p * 2 + nxt) * 8u;
            const uint32_t vv  = __float_as_uint(v);
            asm volatile("st.async.shared::cluster.mbarrier::complete_tx::bytes.u32 [%0], %1, [%2];"
                         :: "r"(self_sm + slot), "r"(vv), "r"(self_mb + mbo) : "memory");
            asm volatile("st.async.shared::cluster.mbarrier::complete_tx::bytes.u32 [%0], %1, [%2];"
                         :: "r"(peer_sm + slot), "r"(vv), "r"(peer_mb + mbo) : "memory");

            // off the critical path: persist for the head kernel
            g_h[((size_t)s * BATCH + g * 4 + row) * HID + col] = __float2half(v);
        }

        // x-terms for step s+1 (independent math; hidden under the loop)
        if (havex) {
            cA = fmaf(xnA.x, wih0, fmaf(xnA.y, wih1, biasv));
            cB = fmaf(xnB.x, wih0, fmaf(xnB.y, wih1, biasv));
        }
    }

    // keep smem/mbars alive until peer's trailing async traffic drains
    asm volatile("barrier.cluster.arrive.aligned;" ::: "memory");
    asm volatile("barrier.cluster.wait.aligned;"   ::: "memory");
}

// ---------------------------------------------------------------------------
// Head: logits = h @ lin_W^T + lin_b, softmax over I=2.
// One warp per FOUR (s,b) rows; 4 independent uint4 loads issued up front
// (2x the MLP of the R11 head; head is DRAM-bound at 38% of spec).
// ---------------------------------------------------------------------------
__global__ void __launch_bounds__(256)
rnn_head_kernel(const float* __restrict__ lin_W,
                const float* __restrict__ lin_b,
                float* __restrict__ out)
{
    __shared__ float w0s[HID], w1s[HID], lbs[2];
    const int tid = threadIdx.x;
    if (tid < HID) { w0s[tid] = lin_W[tid]; w1s[tid] = lin_W[HID + tid]; }
    if (tid < 2)   lbs[tid] = lin_b[tid];
    __syncthreads();

    const int lane = tid & 31;
    const size_t sb0 = (size_t)blockIdx.x * 32 + (tid >> 5) * 4;

    // 4 rows' loads issued back-to-back (4x MLP)
    uint4 v0 = *(const uint4*)(g_h + (sb0 + 0) * HID + lane * 8);
    uint4 v1 = *(const uint4*)(g_h + (sb0 + 1) * HID + lane * 8);
    uint4 v2 = *(const uint4*)(g_h + (sb0 + 2) * HID + lane * 8);
    uint4 v3 = *(const uint4*)(g_h + (sb0 + 3) * HID + lane * 8);

    float4 wa0 = *(const float4*)(w0s + lane * 8);
    float4 wa1 = *(const float4*)(w0s + lane * 8 + 4);
    float4 wb0 = *(const float4*)(w1s + lane * 8);
    float4 wb1 = *(const float4*)(w1s + lane * 8 + 4);

    #pragma unroll
    for (int r = 0; r < 4; ++r) {
        uint4 v = (r == 0) ? v0 : (r == 1) ? v1 : (r == 2) ? v2 : v3;
        float2 h0 = __half22float2(*(const __half2*)&v.x);
        float2 h1 = __half22float2(*(const __half2*)&v.y);
        float2 h2 = __half22float2(*(const __half2*)&v.z);
        float2 h3 = __half22float2(*(const __half2*)&v.w);

        float acc0 = h0.x*wa0.x + h0.y*wa0.y + h1.x*wa0.z + h1.y*wa0.w
                   + h2.x*wa1.x + h2.y*wa1.y + h3.x*wa1.z + h3.y*wa1.w;
        float acc1 = h0.x*wb0.x + h0.y*wb0.y + h1.x*wb0.z + h1.y*wb0.w
                   + h2.x*wb1.x + h2.y*wb1.y + h3.x*wb1.z + h3.y*wb1.w;

        #pragma unroll
        for (int m = 16; m; m >>= 1) {
            acc0 += __shfl_xor_sync(0xffffffffu, acc0, m);
            acc1 += __shfl_xor_sync(0xffffffffu, acc1, m);
        }
        if (lane == 0) {
            float l0 = acc0 + lbs[0], l1 = acc1 + lbs[1];
            float mx = fmaxf(l0, l1);
            float e0 = expf(l0 - mx), e1 = expf(l1 - mx);
            float inv = 1.0f / (e0 + e1);
            float2 o; o.x = e0 * inv; o.y = e1 * inv;
            *(float2*)(out + (sb0 + r) * 2) = o;
        }
    }
}

// ---------------------------------------------------------------------------
extern "C" void kernel_launch(void* const* d_in, const int* in_sizes, int n_in,
                              void* d_out, int out_size)
{
    (void)in_sizes; (void)n_in; (void)out_size;
    const float* data  = (const float*)d_in[0];
    const float* W_ih  = (const float*)d_in[1];
    const float* b_ih  = (const float*)d_in[2];
    const float* W_hh  = (const float*)d_in[3];
    const float* b_hh  = (const float*)d_in[4];
    const float* lin_W = (const float*)d_in[5];
    const float* lin_b = (const float*)d_in[6];
    float* out = (float*)d_out;

    rnn_scan_kernel<<<128, NTHREADS>>>(data, W_ih, b_ih, W_hh, b_hh);
    // 262144 (s,b) rows, 4 per warp, 8 warps per block -> 8192 blocks
    rnn_head_kernel<<<(S_LEN * BATCH) / 32, 256>>>(lin_W, lin_b, out);
}

// round 15
// speedup vs baseline: 2.2340x; 1.0003x over previous
#include <cuda_runtime.h>
#include <cuda_fp16.h>
#include <cstdint>
#include <cstddef>

// ---------------------------------------------------------------------------
// data [S=1024, B=256, I=2], W_ih [256,2], b_ih[256], W_hh [256,256],
// b_hh[256], lin_W [2,256], lin_b[2]; out = softmax(h @ lin_W^T + lin_b).
//
// R15 = R11/R7 scan kernel BYTE-IDENTICAL (frozen; reproduces ~1245 us)
//     + head kernel with 8 rows/warp (8 independent uint4 loads, 2x MLP
//       vs R14; head was DRAM-latency-bound at 3.73 TB/s / 46.7%).
// ---------------------------------------------------------------------------

#define S_LEN    1024
#define BATCH    256
#define HID      256
#define NTHREADS 256

#define HROW   264                  // 128 | pad4 | 128 | pad4
#define HPBUF  (4*HROW)             // 4 batch rows
#define SMEM_FLOATS (2*HPBUF)       // 2112 floats = 8448 B

__device__ __half g_h[(size_t)S_LEN * BATCH * HID];   // 134 MB fp16 scratch

typedef unsigned long long u64;

__device__ __forceinline__ void fma2(u64& acc, u64 a, u64 b) {
    asm("fma.rn.f32x2 %0, %1, %2, %0;" : "+l"(acc) : "l"(a), "l"(b));
}
__device__ __forceinline__ u64 add2(u64 a, u64 b) {
    u64 r; asm("add.rn.f32x2 %0, %1, %2;" : "=l"(r) : "l"(a), "l"(b)); return r;
}
__device__ __forceinline__ float pairsum(u64 v) {
    return __uint_as_float((unsigned)(v & 0xffffffffull)) +
           __uint_as_float((unsigned)(v >> 32));
}
__device__ __forceinline__ float fast_tanh(float x) {
    float e = __expf(-2.0f * x);
    return __fdividef(1.0f - e, 1.0f + e);
}
__device__ __forceinline__ void mbar_wait(uint32_t mba, uint32_t par) {
    asm volatile(
        "{\n\t.reg .pred P;\n"
        "WL_%=:\n\t"
        "mbarrier.try_wait.parity.acquire.cluster.shared::cta.b64 P, [%0], %1, 0x989680;\n\t"
        "@P bra.uni WD_%=;\n\t"
        "bra.uni WL_%=;\n"
        "WD_%=:\n\t}"
        :: "r"(mba), "r"(par) : "memory");
}

__global__ void __launch_bounds__(NTHREADS, 1) __cluster_dims__(2, 1, 1)
rnn_scan_kernel(const float* __restrict__ data,
                const float* __restrict__ W_ih,
                const float* __restrict__ b_ih,
                const float* __restrict__ W_hh,
                const float* __restrict__ b_hh)
{
    __shared__ __align__(16) float sm[SMEM_FLOATS];
    __shared__ __align__(8)  unsigned long long mb[4];   // [pair*2 + buf]

    const int tid = threadIdx.x;
    uint32_t rank;
    asm("mov.u32 %0, %%cluster_ctarank;" : "=r"(rank));
    const int g   = blockIdx.x >> 1;          // batch group of 4 rows
    const int hh  = tid >> 1;                 // column within half
    const int kc  = tid & 1;                  // k-half this thread reduces
    const int col = (int)rank * 128 + hh;     // global output column
    const int rowA = kc;                      // row finalized in phase A
    const int rowB = 2 + kc;                  // row finalized in phase B

    // ---- init: zero h buf0 ----
    for (int i = tid; i < HPBUF; i += NTHREADS) sm[i] = 0.0f;

    // ---- W_hh half-row -> 64 u64 registers ----
    u64 W[64];
    {
        const float* wp = W_hh + (size_t)col * HID + kc * 128;
        #pragma unroll
        for (int j = 0; j < 32; ++j) {
            ulonglong2 t = *(const ulonglong2*)(wp + 4 * j);
            W[2 * j] = t.x; W[2 * j + 1] = t.y;
        }
    }
    const float biasv = b_ih[col] + b_hh[col];
    const float wih0  = W_ih[col * 2 + 0];
    const float wih1  = W_ih[col * 2 + 1];

    uint32_t sm_u32, mb_u32;
    asm("{ .reg .u64 t; cvta.to.shared.u64 t, %1; cvt.u32.u64 %0, t; }"
        : "=r"(sm_u32) : "l"(sm));
    asm("{ .reg .u64 t; cvta.to.shared.u64 t, %1; cvt.u32.u64 %0, t; }"
        : "=r"(mb_u32) : "l"(mb));
    uint32_t self_sm, self_mb, peer_sm, peer_mb;
    asm("mapa.shared::cluster.u32 %0, %1, %2;"
        : "=r"(self_sm) : "r"(sm_u32), "r"(rank));
    asm("mapa.shared::cluster.u32 %0, %1, %2;"
        : "=r"(self_mb) : "r"(mb_u32), "r"(rank));
    asm("mapa.shared::cluster.u32 %0, %1, %2;"
        : "=r"(peer_sm) : "r"(sm_u32), "r"(rank ^ 1u));
    asm("mapa.shared::cluster.u32 %0, %1, %2;"
        : "=r"(peer_mb) : "r"(mb_u32), "r"(rank ^ 1u));

    // count = 1: only tid0's expect_tx arrive; everything else is tx bytes
    if (tid < 4)
        asm volatile("mbarrier.init.shared.b64 [%0], %1;"
                     :: "r"(mb_u32 + (uint32_t)tid * 8u), "r"(1u) : "memory");
    __syncthreads();
    // peer mbars + zeroed h must be live before any st.async traffic
    asm volatile("barrier.cluster.arrive.aligned;" ::: "memory");
    asm volatile("barrier.cluster.wait.aligned;"   ::: "memory");

    // x-term constants for step 0: x0 = [1, 0]
    float cA = wih0 + biasv;
    float cB = wih0 + biasv;

    for (int s = 0; s < S_LEN; ++s) {
        const int cur = s & 1, nxt = cur ^ 1;
        const uint32_t par = (uint32_t)(((s - 1) >> 1) & 1);

        // arm both pair-barriers for buf[nxt] (2048B of st.async each)
        if (tid == 0) {
            asm volatile("mbarrier.arrive.expect_tx.shared.b64 _, [%0], %1;"
                         :: "r"(mb_u32 + (uint32_t)(0 + nxt) * 8u), "r"(2048u) : "memory");
            asm volatile("mbarrier.arrive.expect_tx.shared.b64 _, [%0], %1;"
                         :: "r"(mb_u32 + (uint32_t)(2 + nxt) * 8u), "r"(2048u) : "memory");
        }

        // prefetch x for step s+1 (x[s+1] = data[s]) into registers
        float2 xnA, xnB;
        const bool havex = (s < S_LEN - 1);
        if (havex) {
            const float* xb = data + (size_t)s * BATCH * 2;
            xnA = *(const float2*)(xb + (g * 4 + rowA) * 2);
            xnB = *(const float2*)(xb + (g * 4 + rowB) * 2);
        }

        #pragma unroll
        for (int p = 0; p < 2; ++p) {
            // gate: rows 2p,2p+1 of h_s fully present (self + peer st.async)
            if (s > 0) mbar_wait(mb_u32 + (uint32_t)(p * 2 + cur) * 8u, par);

            // ---- FMA rows 2p, 2p+1 over own k-half ----
            const float* hb = sm + cur * HPBUF + p * 2 * HROW + kc * 132;
            u64 a0 = 0, a1 = 0, b0 = 0, b1 = 0;
            #pragma unroll
            for (int j = 0; j < 32; ++j) {
                const int k = 4 * j;
                ulonglong2 h0 = *(const ulonglong2*)(hb + k);
                ulonglong2 h1 = *(const ulonglong2*)(hb + HROW + k);
                fma2(a0, W[2*j], h0.x); fma2(a1, W[2*j+1], h0.y);
                fma2(b0, W[2*j], h1.x); fma2(b1, W[2*j+1], h1.y);
            }
            float p0 = pairsum(add2(a0, a1));   // partial, row 2p
            float p1 = pairsum(add2(b0, b1));   // partial, row 2p+1

            // cross-k-half reduction with partner lane (lane^1, same column)
            float q0 = __shfl_xor_sync(0xffffffffu, p0, 1);
            float q1 = __shfl_xor_sync(0xffffffffu, p1, 1);
            float t  = (kc == 0) ? (p0 + q0) : (p1 + q1);
            float v  = fast_tanh(((p == 0) ? cA : cB) + t);

            // ---- publish row (2p + kc) of h_{s+1}: self + peer st.async ----
            const int row = 2 * p + kc;
            const uint32_t slot =
                (uint32_t)(nxt * HPBUF + row * HROW + (int)rank * 132 + hh) * 4u;
            const uint32_t mbo = (uint32_t)(p * 2 + nxt) * 8u;
            const uint32_t vv  = __float_as_uint(v);
            asm volatile("st.async.shared::cluster.mbarrier::complete_tx::bytes.u32 [%0], %1, [%2];"
                         :: "r"(self_sm + slot), "r"(vv), "r"(self_mb + mbo) : "memory");
            asm volatile("st.async.shared::cluster.mbarrier::complete_tx::bytes.u32 [%0], %1, [%2];"
                         :: "r"(peer_sm + slot), "r"(vv), "r"(peer_mb + mbo) : "memory");

            // off the critical path: persist for the head kernel
            g_h[((size_t)s * BATCH + g * 4 + row) * HID + col] = __float2half(v);
        }

        // x-terms for step s+1 (independent math; hidden under the loop)
        if (havex) {
            cA = fmaf(xnA.x, wih0, fmaf(xnA.y, wih1, biasv));
            cB = fmaf(xnB.x, wih0, fmaf(xnB.y, wih1, biasv));
        }
    }

    // keep smem/mbars alive until peer's trailing async traffic drains
    asm volatile("barrier.cluster.arrive.aligned;" ::: "memory");
    asm volatile("barrier.cluster.wait.aligned;"   ::: "memory");
}

// ---------------------------------------------------------------------------
// Head: logits = h @ lin_W^T + lin_b, softmax over I=2.
// One warp per EIGHT (s,b) rows; 8 independent uint4 loads issued up front
// (2x the MLP of the R14 head; head is DRAM-latency-bound at 46.7% of spec).
// ---------------------------------------------------------------------------
__global__ void __launch_bounds__(256)
rnn_head_kernel(const float* __restrict__ lin_W,
                const float* __restrict__ lin_b,
                float* __restrict__ out)
{
    __shared__ float w0s[HID], w1s[HID], lbs[2];
    const int tid = threadIdx.x;
    if (tid < HID) { w0s[tid] = lin_W[tid]; w1s[tid] = lin_W[HID + tid]; }
    if (tid < 2)   lbs[tid] = lin_b[tid];
    __syncthreads();

    const int lane = tid & 31;
    const size_t sb0 = (size_t)blockIdx.x * 64 + (tid >> 5) * 8;

    // 8 rows' loads issued back-to-back (8x MLP)
    uint4 v[8];
    #pragma unroll
    for (int r = 0; r < 8; ++r)
        v[r] = *(const uint4*)(g_h + (sb0 + r) * HID + lane * 8);

    float4 wa0 = *(const float4*)(w0s + lane * 8);
    float4 wa1 = *(const float4*)(w0s + lane * 8 + 4);
    float4 wb0 = *(const float4*)(w1s + lane * 8);
    float4 wb1 = *(const float4*)(w1s + lane * 8 + 4);

    #pragma unroll
    for (int r = 0; r < 8; ++r) {
        float2 h0 = __half22float2(*(const __half2*)&v[r].x);
        float2 h1 = __half22float2(*(const __half2*)&v[r].y);
        float2 h2 = __half22float2(*(const __half2*)&v[r].z);
        float2 h3 = __half22float2(*(const __half2*)&v[r].w);

        float acc0 = h0.x*wa0.x + h0.y*wa0.y + h1.x*wa0.z + h1.y*wa0.w
                   + h2.x*wa1.x + h2.y*wa1.y + h3.x*wa1.z + h3.y*wa1.w;
        float acc1 = h0.x*wb0.x + h0.y*wb0.y + h1.x*wb0.z + h1.y*wb0.w
                   + h2.x*wb1.x + h2.y*wb1.y + h3.x*wb1.z + h3.y*wb1.w;

        #pragma unroll
        for (int m = 16; m; m >>= 1) {
            acc0 += __shfl_xor_sync(0xffffffffu, acc0, m);
            acc1 += __shfl_xor_sync(0xffffffffu, acc1, m);
        }
        if (lane == 0) {
            float l0 = acc0 + lbs[0], l1 = acc1 + lbs[1];
            float mx = fmaxf(l0, l1);
            float e0 = expf(l0 - mx), e1 = expf(l1 - mx);
            float inv = 1.0f / (e0 + e1);
            float2 o; o.x = e0 * inv; o.y = e1 * inv;
            *(float2*)(out + (sb0 + r) * 2) = o;
        }
    }
}

// ---------------------------------------------------------------------------
extern "C" void kernel_launch(void* const* d_in, const int* in_sizes, int n_in,
                              void* d_out, int out_size)
{
    (void)in_sizes; (void)n_in; (void)out_size;
    const float* data  = (const float*)d_in[0];
    const float* W_ih  = (const float*)d_in[1];
    const float* b_ih  = (const float*)d_in[2];
    const float* W_hh  = (const float*)d_in[3];
    const float* b_hh  = (const float*)d_in[4];
    const float* lin_W = (const float*)d_in[5];
    const float* lin_b = (const float*)d_in[6];
    float* out = (float*)d_out;

    rnn_scan_kernel<<<128, NTHREADS>>>(data, W_ih, b_ih, W_hh, b_hh);
    // 262144 (s,b) rows, 8 per warp, 8 warps per block -> 4096 blocks
    rnn_head_kernel<<<(S_LEN * BATCH) / 64, 256>>>(lin_W, lin_b, out);
}

// round 16
// speedup vs baseline: 2.2401x; 1.0027x over previous
#include <cuda_runtime.h>
#include <cuda_fp16.h>
#include <cstdint>
#include <cstddef>

// ---------------------------------------------------------------------------
// data [S=1024, B=256, I=2], W_ih [256,2], b_ih[256], W_hh [256,256],
// b_hh[256], lin_W [2,256], lin_b[2]; out = softmax(h @ lin_W^T + lin_b).
//
// R16 (final) = R11/R7 scan kernel BYTE-IDENTICAL (frozen; ~1245 us,
// reproduced 3x; all structural variants R8-R13 regressed 300-1600 us)
// + R14 head (4 rows/warp = measured MLP/occupancy optimum; 8 rows was
//   worse) with __ldcs streaming loads on the single-use g_h stream.
// ---------------------------------------------------------------------------

#define S_LEN    1024
#define BATCH    256
#define HID      256
#define NTHREADS 256

#define HROW   264                  // 128 | pad4 | 128 | pad4
#define HPBUF  (4*HROW)             // 4 batch rows
#define SMEM_FLOATS (2*HPBUF)       // 2112 floats = 8448 B

__device__ __half g_h[(size_t)S_LEN * BATCH * HID];   // 134 MB fp16 scratch

typedef unsigned long long u64;

__device__ __forceinline__ void fma2(u64& acc, u64 a, u64 b) {
    asm("fma.rn.f32x2 %0, %1, %2, %0;" : "+l"(acc) : "l"(a), "l"(b));
}
__device__ __forceinline__ u64 add2(u64 a, u64 b) {
    u64 r; asm("add.rn.f32x2 %0, %1, %2;" : "=l"(r) : "l"(a), "l"(b)); return r;
}
__device__ __forceinline__ float pairsum(u64 v) {
    return __uint_as_float((unsigned)(v & 0xffffffffull)) +
           __uint_as_float((unsigned)(v >> 32));
}
__device__ __forceinline__ float fast_tanh(float x) {
    float e = __expf(-2.0f * x);
    return __fdividef(1.0f - e, 1.0f + e);
}
__device__ __forceinline__ void mbar_wait(uint32_t mba, uint32_t par) {
    asm volatile(
        "{\n\t.reg .pred P;\n"
        "WL_%=:\n\t"
        "mbarrier.try_wait.parity.acquire.cluster.shared::cta.b64 P, [%0], %1, 0x989680;\n\t"
        "@P bra.uni WD_%=;\n\t"
        "bra.uni WL_%=;\n"
        "WD_%=:\n\t}"
        :: "r"(mba), "r"(par) : "memory");
}

__global__ void __launch_bounds__(NTHREADS, 1) __cluster_dims__(2, 1, 1)
rnn_scan_kernel(const float* __restrict__ data,
                const float* __restrict__ W_ih,
                const float* __restrict__ b_ih,
                const float* __restrict__ W_hh,
                const float* __restrict__ b_hh)
{
    __shared__ __align__(16) float sm[SMEM_FLOATS];
    __shared__ __align__(8)  unsigned long long mb[4];   // [pair*2 + buf]

    const int tid = threadIdx.x;
    uint32_t rank;
    asm("mov.u32 %0, %%cluster_ctarank;" : "=r"(rank));
    const int g   = blockIdx.x >> 1;          // batch group of 4 rows
    const int hh  = tid >> 1;                 // column within half
    const int kc  = tid & 1;                  // k-half this thread reduces
    const int col = (int)rank * 128 + hh;     // global output column
    const int rowA = kc;                      // row finalized in phase A
    const int rowB = 2 + kc;                  // row finalized in phase B

    // ---- init: zero h buf0 ----
    for (int i = tid; i < HPBUF; i += NTHREADS) sm[i] = 0.0f;

    // ---- W_hh half-row -> 64 u64 registers ----
    u64 W[64];
    {
        const float* wp = W_hh + (size_t)col * HID + kc * 128;
        #pragma unroll
        for (int j = 0; j < 32; ++j) {
            ulonglong2 t = *(const ulonglong2*)(wp + 4 * j);
            W[2 * j] = t.x; W[2 * j + 1] = t.y;
        }
    }
    const float biasv = b_ih[col] + b_hh[col];
    const float wih0  = W_ih[col * 2 + 0];
    const float wih1  = W_ih[col * 2 + 1];

    uint32_t sm_u32, mb_u32;
    asm("{ .reg .u64 t; cvta.to.shared.u64 t, %1; cvt.u32.u64 %0, t; }"
        : "=r"(sm_u32) : "l"(sm));
    asm("{ .reg .u64 t; cvta.to.shared.u64 t, %1; cvt.u32.u64 %0, t; }"
        : "=r"(mb_u32) : "l"(mb));
    uint32_t self_sm, self_mb, peer_sm, peer_mb;
    asm("mapa.shared::cluster.u32 %0, %1, %2;"
        : "=r"(self_sm) : "r"(sm_u32), "r"(rank));
    asm("mapa.shared::cluster.u32 %0, %1, %2;"
        : "=r"(self_mb) : "r"(mb_u32), "r"(rank));
    asm("mapa.shared::cluster.u32 %0, %1, %2;"
        : "=r"(peer_sm) : "r"(sm_u32), "r"(rank ^ 1u));
    asm("mapa.shared::cluster.u32 %0, %1, %2;"
        : "=r"(peer_mb) : "r"(mb_u32), "r"(rank ^ 1u));

    // count = 1: only tid0's expect_tx arrive; everything else is tx bytes
    if (tid < 4)
        asm volatile("mbarrier.init.shared.b64 [%0], %1;"
                     :: "r"(mb_u32 + (uint32_t)tid * 8u), "r"(1u) : "memory");
    __syncthreads();
    // peer mbars + zeroed h must be live before any st.async traffic
    asm volatile("barrier.cluster.arrive.aligned;" ::: "memory");
    asm volatile("barrier.cluster.wait.aligned;"   ::: "memory");

    // x-term constants for step 0: x0 = [1, 0]
    float cA = wih0 + biasv;
    float cB = wih0 + biasv;

    for (int s = 0; s < S_LEN; ++s) {
        const int cur = s & 1, nxt = cur ^ 1;
        const uint32_t par = (uint32_t)(((s - 1) >> 1) & 1);

        // arm both pair-barriers for buf[nxt] (2048B of st.async each)
        if (tid == 0) {
            asm volatile("mbarrier.arrive.expect_tx.shared.b64 _, [%0], %1;"
                         :: "r"(mb_u32 + (uint32_t)(0 + nxt) * 8u), "r"(2048u) : "memory");
            asm volatile("mbarrier.arrive.expect_tx.shared.b64 _, [%0], %1;"
                         :: "r"(mb_u32 + (uint32_t)(2 + nxt) * 8u), "r"(2048u) : "memory");
        }

        // prefetch x for step s+1 (x[s+1] = data[s]) into registers
        float2 xnA, xnB;
        const bool havex = (s < S_LEN - 1);
        if (havex) {
            const float* xb = data + (size_t)s * BATCH * 2;
            xnA = *(const float2*)(xb + (g * 4 + rowA) * 2);
            xnB = *(const float2*)(xb + (g * 4 + rowB) * 2);
        }

        #pragma unroll
        for (int p = 0; p < 2; ++p) {
            // gate: rows 2p,2p+1 of h_s fully present (self + peer st.async)
            if (s > 0) mbar_wait(mb_u32 + (uint32_t)(p * 2 + cur) * 8u, par);

            // ---- FMA rows 2p, 2p+1 over own k-half ----
            const float* hb = sm + cur * HPBUF + p * 2 * HROW + kc * 132;
            u64 a0 = 0, a1 = 0, b0 = 0, b1 = 0;
            #pragma unroll
            for (int j = 0; j < 32; ++j) {
                const int k = 4 * j;
                ulonglong2 h0 = *(const ulonglong2*)(hb + k);
                ulonglong2 h1 = *(const ulonglong2*)(hb + HROW + k);
                fma2(a0, W[2*j], h0.x); fma2(a1, W[2*j+1], h0.y);
                fma2(b0, W[2*j], h1.x); fma2(b1, W[2*j+1], h1.y);
            }
            float p0 = pairsum(add2(a0, a1));   // partial, row 2p
            float p1 = pairsum(add2(b0, b1));   // partial, row 2p+1

            // cross-k-half reduction with partner lane (lane^1, same column)
            float q0 = __shfl_xor_sync(0xffffffffu, p0, 1);
            float q1 = __shfl_xor_sync(0xffffffffu, p1, 1);
            float t  = (kc == 0) ? (p0 + q0) : (p1 + q1);
            float v  = fast_tanh(((p == 0) ? cA : cB) + t);

            // ---- publish row (2p + kc) of h_{s+1}: self + peer st.async ----
            const int row = 2 * p + kc;
            const uint32_t slot =
                (uint32_t)(nxt * HPBUF + row * HROW + (int)rank * 132 + hh) * 4u;
            const uint32_t mbo = (uint32_t)(p * 2 + nxt) * 8u;
            const uint32_t vv  = __float_as_uint(v);
            asm volatile("st.async.shared::cluster.mbarrier::complete_tx::bytes.u32 [%0], %1, [%2];"
                         :: "r"(self_sm + slot), "r"(vv), "r"(self_mb + mbo) : "memory");
            asm volatile("st.async.shared::cluster.mbarrier::complete_tx::bytes.u32 [%0], %1, [%2];"
                         :: "r"(peer_sm + slot), "r"(vv), "r"(peer_mb + mbo) : "memory");

            // off the critical path: persist for the head kernel
            g_h[((size_t)s * BATCH + g * 4 + row) * HID + col] = __float2half(v);
        }

        // x-terms for step s+1 (independent math; hidden under the loop)
        if (havex) {
            cA = fmaf(xnA.x, wih0, fmaf(xnA.y, wih1, biasv));
            cB = fmaf(xnB.x, wih0, fmaf(xnB.y, wih1, biasv));
        }
    }

    // keep smem/mbars alive until peer's trailing async traffic drains
    asm volatile("barrier.cluster.arrive.aligned;" ::: "memory");
    asm volatile("barrier.cluster.wait.aligned;"   ::: "memory");
}

// ---------------------------------------------------------------------------
// Head: logits = h @ lin_W^T + lin_b, softmax over I=2.
// One warp per FOUR (s,b) rows (measured MLP/occupancy optimum);
// __ldcs streaming loads — g_h is read exactly once, evict-first keeps
// the single-use 134 MB stream from thrashing L2.
// ---------------------------------------------------------------------------
__global__ void __launch_bounds__(256)
rnn_head_kernel(const float* __restrict__ lin_W,
                const float* __restrict__ lin_b,
                float* __restrict__ out)
{
    __shared__ float w0s[HID], w1s[HID], lbs[2];
    const int tid = threadIdx.x;
    if (tid < HID) { w0s[tid] = lin_W[tid]; w1s[tid] = lin_W[HID + tid]; }
    if (tid < 2)   lbs[tid] = lin_b[tid];
    __syncthreads();

    const int lane = tid & 31;
    const size_t sb0 = (size_t)blockIdx.x * 32 + (tid >> 5) * 4;

    // 4 rows' loads issued back-to-back, streaming (evict-first)
    uint4 v0 = __ldcs((const uint4*)(g_h + (sb0 + 0) * HID + lane * 8));
    uint4 v1 = __ldcs((const uint4*)(g_h + (sb0 + 1) * HID + lane * 8));
    uint4 v2 = __ldcs((const uint4*)(g_h + (sb0 + 2) * HID + lane * 8));
    uint4 v3 = __ldcs((const uint4*)(g_h + (sb0 + 3) * HID + lane * 8));

    float4 wa0 = *(const float4*)(w0s + lane * 8);
    float4 wa1 = *(const float4*)(w0s + lane * 8 + 4);
    float4 wb0 = *(const float4*)(w1s + lane * 8);
    float4 wb1 = *(const float4*)(w1s + lane * 8 + 4);

    #pragma unroll
    for (int r = 0; r < 4; ++r) {
        uint4 v = (r == 0) ? v0 : (r == 1) ? v1 : (r == 2) ? v2 : v3;
        float2 h0 = __half22float2(*(const __half2*)&v.x);
        float2 h1 = __half22float2(*(const __half2*)&v.y);
        float2 h2 = __half22float2(*(const __half2*)&v.z);
        float2 h3 = __half22float2(*(const __half2*)&v.w);

        float acc0 = h0.x*wa0.x + h0.y*wa0.y + h1.x*wa0.z + h1.y*wa0.w
                   + h2.x*wa1.x + h2.y*wa1.y + h3.x*wa1.z + h3.y*wa1.w;
        float acc1 = h0.x*wb0.x + h0.y*wb0.y + h1.x*wb0.z + h1.y*wb0.w
                   + h2.x*wb1.x + h2.y*wb1.y + h3.x*wb1.z + h3.y*wb1.w;

        #pragma unroll
        for (int m = 16; m; m >>= 1) {
            acc0 += __shfl_xor_sync(0xffffffffu, acc0, m);
            acc1 += __shfl_xor_sync(0xffffffffu, acc1, m);
        }
        if (lane == 0) {
            float l0 = acc0 + lbs[0], l1 = acc1 + lbs[1];
            float mx = fmaxf(l0, l1);
            float e0 = expf(l0 - mx), e1 = expf(l1 - mx);
            float inv = 1.0f / (e0 + e1);
            float2 o; o.x = e0 * inv; o.y = e1 * inv;
            *(float2*)(out + (sb0 + r) * 2) = o;
        }
    }
}

// ---------------------------------------------------------------------------
extern "C" void kernel_launch(void* const* d_in, const int* in_sizes, int n_in,
                              void* d_out, int out_size)
{
    (void)in_sizes; (void)n_in; (void)out_size;
    const float* data  = (const float*)d_in[0];
    const float* W_ih  = (const float*)d_in[1];
    const float* b_ih  = (const float*)d_in[2];
    const float* W_hh  = (const float*)d_in[3];
    const float* b_hh  = (const float*)d_in[4];
    const float* lin_W = (const float*)d_in[5];
    const float* lin_b = (const float*)d_in[6];
    float* out = (float*)d_out;

    rnn_scan_kernel<<<128, NTHREADS>>>(data, W_ih, b_ih, W_hh, b_hh);
    // 262144 (s,b) rows, 4 per warp, 8 warps per block -> 8192 blocks
    rnn_head_kernel<<<(S_LEN * BATCH) / 32, 256>>>(lin_W, lin_b, out);
}